// round 12
// baseline (speedup 1.0000x reference)
#include <cuda_runtime.h>

#define NROWS   2048
#define NCOLS   9605
#define ROWS_PB 4
#define NBLK    (NROWS / ROWS_PB)            // 512
#define NTHR    256
#define F4_PB   (ROWS_PB * NCOLS / 4)        // 9605 float4 per block
#define STG_F4  NTHR                          // 256 float4 per stage
#define NST     ((F4_PB + STG_F4 - 1) / STG_F4)  // 38 stages (last partial)
#define S       4                             // pipeline depth
#define CAPS    160
#define CLIPV   0.05f
#define X_TH    2.58f                         // E[cand/row] ~47; exact fallback

__device__ double   g_part[NBLK];
__device__ unsigned g_done;                   // static zero; last block resets

// --- cp.async helpers -------------------------------------------------------
__device__ __forceinline__ void cpa16(unsigned saddr, const void* gaddr, int pred) {
    asm volatile("{\n\t.reg .pred p;\n\tsetp.ne.b32 p, %2, 0;\n\t"
                 "@p cp.async.cg.shared.global [%0], [%1], 16;\n\t}"
                 :: "r"(saddr), "l"(gaddr), "r"(pred));
}
__device__ __forceinline__ void cpa_commit() {
    asm volatile("cp.async.commit_group;");
}
template <int N>
__device__ __forceinline__ void cpa_wait() {
    asm volatile("cp.async.wait_group %0;" :: "n"(N));
}

// --- math (lg2 units; ONE formula used everywhere for consistency) ----------
__device__ __forceinline__ float p_of(float xv) {
    return __fdividef(1.f, 1.f + __expf(-xv));
}
// lg2(arg)*w ; natural-log scaling applied once at the very end
__device__ __forceinline__ float bw2_of(float xv, float yv) {
    float p   = p_of(xv);
    float t   = fmaxf(p - CLIPV, 0.f);        // 1-t == min(1.05-p, 1)
    float t4  = (t * t) * (t * t);
    bool  pos = yv > 0.5f;
    float arg = fmaxf(pos ? p : (1.f - t), 1e-8f);
    float w   = pos ? (1.f - p) : t4;
    return __log2f(arg) * w;
}

__device__ __forceinline__ unsigned long long mk_key(float p, int col) {
    return ((unsigned long long)__float_as_uint(p) << 32) |
           (unsigned long long)(0xFFFFFFFFu - (unsigned)col);
}

__device__ __forceinline__ void ins10(unsigned long long* tk,
                                      unsigned long long key) {
    if (key > tk[9]) {
        tk[9] = key;
#pragma unroll
        for (int i = 9; i > 0; i--)
            if (tk[i] > tk[i - 1]) {
                unsigned long long k0 = tk[i - 1];
                tk[i - 1] = tk[i]; tk[i] = k0;
            }
    }
}

// ---------------------------------------------------------------------------
__global__ void __launch_bounds__(NTHR, 4)
k_main(const float* __restrict__ x, const float* __restrict__ y,
       const int* __restrict__ ci, const int* __restrict__ ri,
       const int* __restrict__ di, const int* __restrict__ wl,
       float* __restrict__ out) {
    const int tid = threadIdx.x;
    const int bid = blockIdx.x;
    const size_t base = (size_t)bid * ROWS_PB * NCOLS;

    __shared__ float4             sx[S][STG_F4];
    __shared__ float4             sy[S][STG_F4];
    __shared__ int                s_cnt[ROWS_PB];
    __shared__ int                s_flags[ROWS_PB];
    __shared__ unsigned long long s_key[ROWS_PB * (CAPS + 1)];
    __shared__ float              s_corr[ROWS_PB];
    __shared__ float              s_warp[NTHR / 32];
    __shared__ int                s_last;

    if (tid < ROWS_PB) { s_cnt[tid] = 0; s_flags[tid] = 0; }
    __syncthreads();

    const float4* __restrict__ x4 = reinterpret_cast<const float4*>(x + base);
    const float4* __restrict__ y4 = reinterpret_cast<const float4*>(y + base);

    const unsigned sxa = (unsigned)__cvta_generic_to_shared(&sx[0][tid]);
    const unsigned sya = (unsigned)__cvta_generic_to_shared(&sy[0][tid]);

    // prologue: stages 0..S-2
#pragma unroll
    for (int j = 0; j < S - 1; j++) {
        int idx4 = j * STG_F4 + tid;
        int pr = idx4 < F4_PB;
        cpa16(sxa + (unsigned)(j & (S - 1)) * (STG_F4 * 16), x4 + idx4, pr);
        cpa16(sya + (unsigned)(j & (S - 1)) * (STG_F4 * 16), y4 + idx4, pr);
        cpa_commit();
    }

    float sum = 0.f;                           // lg2 units
#pragma unroll 1
    for (int j = 0; j < NST; j++) {
        // issue stage j+S-1
        {
            int jn = j + S - 1;
            int idx4 = jn * STG_F4 + tid;
            int pr = (jn < NST) && (idx4 < F4_PB);
            cpa16(sxa + (unsigned)(jn & (S - 1)) * (STG_F4 * 16), x4 + idx4, pr);
            cpa16(sya + (unsigned)(jn & (S - 1)) * (STG_F4 * 16), y4 + idx4, pr);
            cpa_commit();
        }
        cpa_wait<S - 1>();                     // stage j data is in smem

        int idx4 = j * STG_F4 + tid;
        if (idx4 < F4_PB) {
            float4 xv = sx[j & (S - 1)][tid];
            float4 yv = sy[j & (S - 1)][tid];
            float xs[4] = {xv.x, xv.y, xv.z, xv.w};
            float ys[4] = {yv.x, yv.y, yv.z, yv.w};
            int gi0 = idx4 * 4;
#pragma unroll
            for (int k = 0; k < 4; k++) {
                float xvk = xs[k];
                float p   = p_of(xvk);
                float t   = fmaxf(p - CLIPV, 0.f);
                float t4  = (t * t) * (t * t);
                bool  pos = ys[k] > 0.5f;
                float arg = fmaxf(pos ? p : (1.f - t), 1e-8f);
                float w   = pos ? (1.f - p) : t4;
                sum += __log2f(arg) * w;
                if (xvk > X_TH) {              // rare (~0.5%)
                    int gi  = gi0 + k;
                    int rl  = gi / NCOLS;      // 0..3, const div
                    int col = gi - rl * NCOLS;
                    int slot = atomicAdd(&s_cnt[rl], 1);
                    if (slot < CAPS)
                        s_key[rl * (CAPS + 1) + slot] = mk_key(p, col);
                }
            }
        }
    }

    // gt-whitelist flags: 170 probes x 4 rows (rows L2-hot)
    for (int i = tid; i < 170 * ROWS_PB; i += NTHR) {
        int r = i / 170, k = i - r * 170;
        int idx = (k < 30) ? ci[k] : (k < 100) ? ri[k - 30] : di[k - 100];
        if (y[base + (size_t)r * NCOLS + idx] > 0.5f) {
            int bit = (k < 30) ? 1 : (k < 100) ? 2 : 4;
            atomicOr(&s_flags[r], bit);
        }
    }
    __syncthreads();

    // per-row: exact top-10 + sequential rank logic + corrections (lg2 units)
    if (tid < ROWS_PB) {
        const int r = tid;
        const float* xr = x + base + (size_t)r * NCOLS;
        const float* yr = y + base + (size_t)r * NCOLS;
        unsigned long long tk[10];
#pragma unroll
        for (int i = 0; i < 10; i++) tk[i] = 0ULL;

        int n = s_cnt[r];
        if (n < 10 || n > CAPS) {
            // exact fallback (astronomically rare): serial row rescan
            for (int c = 0; c < NCOLS; c++)
                ins10(tk, mk_key(p_of(xr[c]), c));
        } else {
            const unsigned long long* kr = s_key + r * (CAPS + 1);
            for (int i = 0; i < n; i++) ins10(tk, kr[i]);
        }

        int fl = s_flags[r];
        bool has1 = fl & 1, has2 = fl & 2, has3 = fl & 4;
        bool only4 = !(has1 || has2 || has3);
        bool found = false;
        float fac[10];
        int   idx10[10];
#pragma unroll
        for (int q = 0; q < 10; q++) {
            int j = (int)(0xFFFFFFFFu - (unsigned)(tk[q] & 0xFFFFFFFFULL));
            int g = wl[j];
            bool in_map = g > 0;
            bool in_gt  = ((g == 1) && has1) || ((g == 2) && has2) ||
                          ((g == 3) && has3) || ((g == 4) && only4);
            float f = (in_map && only4) ? 0.5f : 1.f;      // ALPHA_OTHER
            if (in_map && !in_gt && !found) f *= 2.f;      // ALPHA1 (first-miss)
            fac[q] = f;
            idx10[q] = j;
            found = found || (in_map && in_gt);
        }
        float extra = found ? 1.f : 2.f;                   // final ALPHA1 pass
        float corr = 0.f;
#pragma unroll
        for (int q = 0; q < 10; q++) {
            int j = idx10[q];
            corr += bw2_of(xr[j], yr[j]) * (fac[q] * extra - 1.f);
        }
        s_corr[r] = corr;
    }

    // block reduction -> per-block double partial (lg2 units)
#pragma unroll
    for (int off = 16; off > 0; off >>= 1)
        sum += __shfl_down_sync(0xFFFFFFFFu, sum, off);
    int lane = tid & 31, wid = tid >> 5;
    if (lane == 0) s_warp[wid] = sum;
    __syncthreads();
    if (tid == 0) {
        float b = 0.f;
#pragma unroll
        for (int i = 0; i < NTHR / 32; i++) b += s_warp[i];
        double tot = (double)b;
#pragma unroll
        for (int r = 0; r < ROWS_PB; r++) tot += (double)s_corr[r];
        g_part[bid] = tot;
        __threadfence();
        unsigned t = atomicAdd(&g_done, 1u);
        s_last = (t == NBLK - 1) ? 1 : 0;
    }
    __syncthreads();

    // last finishing block reduces all 512 partials (deterministic)
    if (s_last) {
        __threadfence();
        double d = g_part[tid] + g_part[tid + NTHR];
        __shared__ double s_dw[NTHR / 32];
#pragma unroll
        for (int off = 16; off > 0; off >>= 1)
            d += __shfl_down_sync(0xFFFFFFFFu, d, off);
        if (lane == 0) s_dw[wid] = d;
        __syncthreads();
        if (tid == 0) {
            double tsum = 0.0;
#pragma unroll
            for (int i = 0; i < NTHR / 32; i++) tsum += s_dw[i];
            out[0] = (float)(-tsum * 0.6931471805599453);  // lg2 -> ln
            g_done = 0;                                    // reset for replay
        }
    }
}

extern "C" void kernel_launch(void* const* d_in, const int* in_sizes, int n_in,
                              void* d_out, int out_size) {
    const float* x  = (const float*)d_in[0];
    const float* y  = (const float*)d_in[1];
    const int*   ci = (const int*)d_in[2];
    const int*   ri = (const int*)d_in[3];
    const int*   di = (const int*)d_in[4];
    const int*   wl = (const int*)d_in[5];

    k_main<<<NBLK, NTHR>>>(x, y, ci, ri, di, wl, (float*)d_out);
}